// round 17
// baseline (speedup 1.0000x reference)
#include <cuda_runtime.h>
#include <cuda_bf16.h>
#include <stdint.h>

#define MAXN 50000
#define MAXE 800000
#define IN_DIM 16
#define HID 64
#define OUT 32
#define SCAN_B 256   // NB = ceil(N/256) must be <= 256

#define FLAG_A (1ULL << 32)
#define FLAG_P (2ULL << 32)

// Scratch (device globals; allocation-free per harness rules)
__device__ __align__(16) int                g_cnt   [MAXN];
__device__ __align__(16) int                g_rowptr[MAXN + 1];
__device__ __align__(16) int                g_cursor[MAXN];
__device__ __align__(16) unsigned long long g_desc  [SCAN_B];
__device__ __align__(16) int                g_csr   [MAXE];
__device__ __align__(16) float              g_dinv  [MAXN];
__device__ __align__(16) float              g_xs    [MAXN * IN_DIM]; // dinv*x
__device__ __align__(16) float              g_g2    [MAXN * OUT];    // dinv*(h@W2)

// K1: zero cnt + lookback descriptors
__global__ void k_zero(int N, int NB) {
    int i = blockIdx.x * blockDim.x + threadIdx.x;
    if (i < N) g_cnt[i] = 0;
    if (i < NB) g_desc[i] = 0ULL;
}

// K2: deg count; 4 edges/thread via int4
__global__ void k_count(const int* __restrict__ dst, int E) {
    int t = blockIdx.x * blockDim.x + threadIdx.x;
    int e = t * 4;
    if (e + 3 < E) {
        int4 d = *(const int4*)&dst[e];
        atomicAdd(&g_cnt[d.x], 1);
        atomicAdd(&g_cnt[d.y], 1);
        atomicAdd(&g_cnt[d.z], 1);
        atomicAdd(&g_cnt[d.w], 1);
    } else {
        for (; e < E; e++) atomicAdd(&g_cnt[dst[e]], 1);
    }
}

// K3: single-pass exclusive scan (decoupled lookback) + finalize
// rowptr/cursor/dinv, and pre-scale xs = dinv * x (node-parallel).
__global__ void k_scan(const float* __restrict__ x, int N, int E) {
    __shared__ int sh[SCAN_B];
    __shared__ int s_prefix;
    int b   = blockIdx.x;
    int tid = threadIdx.x;
    int i   = b * SCAN_B + tid;
    int v   = (i < N) ? g_cnt[i] : 0;

    sh[tid] = v;
    __syncthreads();
    for (int off = 1; off < SCAN_B; off <<= 1) {
        int t = (tid >= off) ? sh[tid - off] : 0;
        __syncthreads();
        sh[tid] += t;
        __syncthreads();
    }
    int incl  = sh[tid];
    int total = sh[SCAN_B - 1];

    if (tid == 0) {
        if (b == 0) {
            atomicExch(&g_desc[0], FLAG_P | (unsigned)total);
            s_prefix = 0;
        } else {
            atomicExch(&g_desc[b], FLAG_A | (unsigned)total);
            int running = 0;
            for (int p = b - 1; p >= 0; p--) {
                unsigned long long st;
                do { st = atomicAdd(&g_desc[p], 0ULL); } while ((st >> 32) == 0);
                running += (int)(unsigned)st;
                if (st & FLAG_P) break;
            }
            atomicExch(&g_desc[b], FLAG_P | (unsigned)(running + total));
            s_prefix = running;
        }
    }
    __syncthreads();
    int prefix = s_prefix;

    if (i < N) {
        int r = prefix + incl - v;
        g_rowptr[i] = r;
        g_cursor[i] = r;
        float dv = rsqrtf((float)v + 1.0f);
        g_dinv[i] = dv;
#pragma unroll
        for (int q = 0; q < IN_DIM / 4; q++) {
            float4 xv = *(const float4*)&x[i * IN_DIM + q * 4];
            xv.x *= dv; xv.y *= dv; xv.z *= dv; xv.w *= dv;
            *(float4*)&g_xs[i * IN_DIM + q * 4] = xv;
        }
    }
    if (i == 0) g_rowptr[N] = E;
}

// K4: CSR fill
__global__ void k_fill(const int* __restrict__ src,
                       const int* __restrict__ dst, int E) {
    int e = blockIdx.x * blockDim.x + threadIdx.x;
    if (e < E) {
        int pos = atomicAdd(&g_cursor[dst[e]], 1);
        g_csr[pos] = src[e];
    }
}

// K5: fused aggregate + MLP. Warp per node (4 nodes sequentially).
//   y_d[dim] = dinv_d * ( xs[node][dim] + sum_{s} xs[s][dim] )
//   h = relu(y@W1+b1); g2 = dinv*(h@W2)
// Half-warps split the edge list (even/odd); lane = h*16 + dim.
__global__ void k_aggmlp(const float* __restrict__ W1,
                         const float* __restrict__ b1,
                         const float* __restrict__ W2, int N) {
    __shared__ float W1s[IN_DIM * HID];   // 4 KB
    __shared__ float W2s[HID * OUT];      // 8 KB
    __shared__ float b1s[HID];
    int tid = threadIdx.x;
    for (int i = tid; i < IN_DIM * HID; i += 256) W1s[i] = W1[i];
    for (int i = tid; i < HID * OUT;   i += 256) W2s[i] = W2[i];
    if (tid < HID) b1s[tid] = b1[tid];
    __syncthreads();

    int w     = tid >> 5;
    int lane  = tid & 31;
    int half  = lane >> 4;        // 0 or 1
    int d     = lane & 15;        // dim
    int node0 = blockIdx.x * 32 + w * 4;

#pragma unroll
    for (int it = 0; it < 4; it++) {
        int node = node0 + it;
        if (node >= N) break;

        float dv  = g_dinv[node];
        int   beg = g_rowptr[node];
        int   end = g_rowptr[node + 1];

        // aggregate: half 0 takes even edges + self term, half 1 odd edges
        float acc = (half == 0) ? g_xs[node * IN_DIM + d] : 0.0f;
        for (int j = beg + half; j < end; j += 2) {
            int s = __ldg(&g_csr[j]);
            acc += __ldg(&g_xs[s * IN_DIM + d]);
        }
        acc += __shfl_xor_sync(0xffffffffu, acc, 16);
        float yv = dv * acc;      // lane k (and k+16) holds y[k&15]

        // GEMM1 + bias + relu: lane computes h cols {lane, lane+32}
        float h0 = b1s[lane], h1 = b1s[lane + 32];
#pragma unroll
        for (int k = 0; k < IN_DIM; k++) {
            float yk = __shfl_sync(0xffffffffu, yv, k);
            h0 += yk * W1s[k * HID + lane];
            h1 += yk * W1s[k * HID + lane + 32];
        }
        h0 = fmaxf(h0, 0.0f);
        h1 = fmaxf(h1, 0.0f);

        // GEMM2: lane computes g2 col = lane
        float acc2 = 0.0f;
#pragma unroll
        for (int k = 0; k < 32; k++) {
            float hk = __shfl_sync(0xffffffffu, h0, k);
            acc2 += hk * W2s[k * OUT + lane];
        }
#pragma unroll
        for (int k = 0; k < 32; k++) {
            float hk = __shfl_sync(0xffffffffu, h1, k);
            acc2 += hk * W2s[(k + 32) * OUT + lane];
        }
        g_g2[node * OUT + lane] = acc2 * dv;
    }
}

// K6: agg2: warp per node; out = dinv*(g2[self] + sum g2[src]) + b2
__global__ void k_agg2(const float* __restrict__ b2,
                       float* __restrict__ out, int N) {
    int gt   = blockIdx.x * blockDim.x + threadIdx.x;
    int node = gt >> 5;
    int lane = gt & 31;
    if (node >= N) return;

    float acc  = g_g2[node * OUT + lane];   // self loop
    float acc2 = 0.0f;
    int beg = g_rowptr[node];
    int end = g_rowptr[node + 1];
    int j = beg;
    for (; j + 1 < end; j += 2) {
        int s0 = __ldg(&g_csr[j]);
        int s1 = __ldg(&g_csr[j + 1]);
        acc  += __ldg(&g_g2[s0 * OUT + lane]);
        acc2 += __ldg(&g_g2[s1 * OUT + lane]);
    }
    if (j < end) {
        int s = __ldg(&g_csr[j]);
        acc += __ldg(&g_g2[s * OUT + lane]);
    }
    out[node * OUT + lane] = (acc + acc2) * g_dinv[node] + b2[lane];
}

extern "C" void kernel_launch(void* const* d_in, const int* in_sizes, int n_in,
                              void* d_out, int out_size) {
    const float* x   = (const float*)d_in[0];
    const int*   ei  = (const int*)d_in[1];     // int32 (JAX x64 disabled)
    const float* W1  = (const float*)d_in[2];
    const float* b1  = (const float*)d_in[3];
    const float* W2  = (const float*)d_in[4];
    const float* b2  = (const float*)d_in[5];
    float*       out = (float*)d_out;

    int N = in_sizes[0] / IN_DIM;     // 50000
    int E = in_sizes[1] / 2;          // 800000
    const int* src = ei;
    const int* dst = ei + E;
    int NB = (N + SCAN_B - 1) / SCAN_B;   // 196 <= 256

    k_zero  <<<(N + 255) / 256, 256>>>(N, NB);
    k_count <<<(E / 4 + 255) / 256, 256>>>(dst, E);
    k_scan  <<<NB, SCAN_B>>>(x, N, E);
    k_fill  <<<(E + 255) / 256, 256>>>(src, dst, E);
    k_aggmlp<<<(N + 31) / 32, 256>>>(W1, b1, W2, N);
    k_agg2  <<<((long long)N * 32 + 255) / 256, 256>>>(b2, out, N);
}